// round 17
// baseline (speedup 1.0000x reference)
#include <cuda_runtime.h>
#include <math.h>
#include <stdint.h>

#define C_DIM 6625
#define H0 3313                     // first-half length (second half = 3312)
#define D_DIM 96
#define N_ROWS 8192
#define EPS_F 1e-7f
#define BLOCK_T 256
#define ROWS_PB 4                   // 8 warps -> 4 rows, 2 warps per row
#define GRID_B (N_ROWS / ROWS_PB)   // 2048 blocks

// Scratch (static device allocation — no dynamic alloc allowed).
__device__ float g_row_loss[N_ROWS];
__device__ int   g_done_count = 0;

__device__ __forceinline__ float max4(float4 q) {
    return fmaxf(fmaxf(q.x, q.y), fmaxf(q.z, q.w));
}

__device__ __forceinline__ float neg_inf() {
    return __int_as_float(0xff800000);
}

__global__ void __launch_bounds__(BLOCK_T, 8)   // force <=32 regs -> 8 blocks/SM
cl_split_kernel(const float* __restrict__ features,
                const float* __restrict__ predicts,
                const float* __restrict__ centers,
                float* __restrict__ out) {
    const int tid  = threadIdx.x;
    const int lane = tid & 31;
    const int warp = tid >> 5;

    __shared__ float s_val[8];
    __shared__ int   s_idx[8];
    __shared__ bool  s_is_last;
    __shared__ float s_red[BLOCK_T];

    // ============ half-row argmax: warp pair (2r, 2r+1) covers row r =========
    {
        const int r_local = warp >> 1;
        const int half    = warp & 1;
        const int row     = blockIdx.x * ROWS_PB + r_local;
        const int start   = half ? H0 : 0;
        const int len     = half ? (C_DIM - H0) : H0;

        const float* __restrict__ p = predicts + (size_t)row * C_DIM + start;

        float best = neg_inf();
        int   bidx = C_DIM;  // sentinel larger than any real index

        // Scalar prologue to 16B alignment (base elem index = row*C_DIM+start).
        const unsigned base_e = (unsigned)row * (unsigned)C_DIM + (unsigned)start;
        const int pro = (int)((0u - base_e) & 3u);
        if (lane < pro) {
            float v = __ldg(p + lane);
            if (v > best) { best = v; bidx = start + lane; }
        }

        const float4* __restrict__ p4 = (const float4*)(p + pro);
        const int nvec  = (len - pro) >> 2;
        const int ibody = (nvec / 96) * 96;     // chunks of 96 vecs (3x32)

        for (int i = lane; i < ibody; i += 96) {
            // three independent 16B loads (imm offsets share one address pair),
            // then a branch-free fmax tree — proven best config (R13)
            float4 q0 = __ldg(p4 + i);
            float4 q1 = __ldg(p4 + i + 32);
            float4 q2 = __ldg(p4 + i + 64);
            float m = fmaxf(fmaxf(max4(q0), max4(q1)), max4(q2));
            if (m > best) {   // rare
                best = m;
                int b0 = start + pro + (i << 2);
                if      (q0.x == m) bidx = b0;
                else if (q0.y == m) bidx = b0 + 1;
                else if (q0.z == m) bidx = b0 + 2;
                else if (q0.w == m) bidx = b0 + 3;
                else if (q1.x == m) bidx = b0 + 128;
                else if (q1.y == m) bidx = b0 + 129;
                else if (q1.z == m) bidx = b0 + 130;
                else if (q1.w == m) bidx = b0 + 131;
                else if (q2.x == m) bidx = b0 + 256;
                else if (q2.y == m) bidx = b0 + 257;
                else if (q2.z == m) bidx = b0 + 258;
                else                bidx = b0 + 259;
            }
        }

        // Remainder vecs.
        for (int i = ibody + lane; i < nvec; i += 32) {
            float4 q = __ldg(p4 + i);
            float m = max4(q);
            if (m > best) {
                best = m;
                int b = start + pro + (i << 2);
                if      (q.x == m) bidx = b;
                else if (q.y == m) bidx = b + 1;
                else if (q.z == m) bidx = b + 2;
                else               bidx = b + 3;
            }
        }

        // Scalar tail (<4 elements).
        for (int c = pro + (nvec << 2) + lane; c < len; c += 32) {
            float v = __ldg(p + c);
            if (v > best) { best = v; bidx = start + c; }
        }

        // Warp argmax reduce: larger value wins; tie -> smaller index.
        #pragma unroll
        for (int off = 16; off > 0; off >>= 1) {
            float ov = __shfl_down_sync(0xffffffffu, best, off);
            int   oi = __shfl_down_sync(0xffffffffu, bidx, off);
            if (ov > best || (ov == best && oi < bidx)) { best = ov; bidx = oi; }
        }
        if (lane == 0) { s_val[warp] = best; s_idx[warp] = bidx; }
    }
    __syncthreads();

    // ============ warps 0-3: combine halves + distance for one row ===========
    if (warp < ROWS_PB) {
        const int row = blockIdx.x * ROWS_PB + warp;

        // Combine the two halves (all lanes compute identically).
        float v0 = s_val[2 * warp],     v1 = s_val[2 * warp + 1];
        int   i0 = s_idx[2 * warp],     i1 = s_idx[2 * warp + 1];
        // half 0 has strictly smaller indices, so tie -> half 0
        const int label = (v1 > v0) ? i1 : i0;

        const float* __restrict__ f   = features + (size_t)row * D_DIM;
        const float* __restrict__ cen = centers  + (size_t)label * D_DIM;
        float acc = 0.0f;
        #pragma unroll
        for (int j = 0; j < D_DIM / 32; j++) {
            int d = lane + j * 32;
            float diff = __ldg(f + d) - __ldg(cen + d);
            acc = fmaf(diff, diff, acc);
        }
        #pragma unroll
        for (int off = 16; off > 0; off >>= 1)
            acc += __shfl_down_sync(0xffffffffu, acc, off);
        if (lane == 0) {
            // label column clips at EPS; the other C-1 masked zeros each clip
            // to EPS and are summed by the reference -> add (C-1)*EPS per row.
            g_row_loss[row] = fmaxf(acc, EPS_F) + (float)(C_DIM - 1) * EPS_F;
        }
    }

    // ================= fused final reduction (last block, fixed order) ========
    __threadfence();
    __syncthreads();
    if (tid == 0) {
        int ticket = atomicAdd(&g_done_count, 1);
        s_is_last = (ticket == GRID_B - 1);
    }
    __syncthreads();

    if (s_is_last) {
        float acc = 0.0f;
        for (int i2 = tid; i2 < N_ROWS; i2 += BLOCK_T)
            acc += g_row_loss[i2];
        s_red[tid] = acc;
        __syncthreads();
        #pragma unroll
        for (int st = BLOCK_T / 2; st > 0; st >>= 1) {
            if (tid < st) s_red[tid] += s_red[tid + st];
            __syncthreads();
        }
        if (tid == 0) {
            out[0] = s_red[0] / (float)N_ROWS;
            g_done_count = 0;  // reset for next graph replay
        }
    }
}

extern "C" void kernel_launch(void* const* d_in, const int* in_sizes, int n_in,
                              void* d_out, int out_size) {
    const float* features = (const float*)d_in[0];  // [32,256,96]
    const float* predicts = (const float*)d_in[1];  // [32,256,6625]
    const float* centers  = (const float*)d_in[2];  // [6625,96]
    float* out = (float*)d_out;

    cl_split_kernel<<<GRID_B, BLOCK_T>>>(features, predicts, centers, out);
}